// round 9
// baseline (speedup 1.0000x reference)
#include <cuda_runtime.h>
#include <math.h>

#define B_ 16
#define L_ 64
#define NLEV 63
#define CAP 512
#define TREE_GRID 592
#define LSTM_GRID 128

// ---------------- device scratch (static globals) --------------------------------
static __device__ __align__(256) float d_xg[B_*L_*4096];
static __device__ __align__(256) float d_hs[B_*L_*1024];
static __device__ __align__(256) float d_cs[B_*L_*1024];
static __device__ __align__(256) float d_nodeh[B_*64*1024];
static __device__ __align__(256) float d_nodec[B_*64*1024];
static __device__ __align__(256) float d_Gp[3][CAP*6144];
static __device__ __align__(256) float d_zero[1024];
static __device__ float d_sc[B_*L_];
static __device__ int   d_npos[B_*64];
static __device__ int   d_nleft[B_*64];
static __device__ int   d_nright[B_*64];
static __device__ int   d_lvl_cnt[NLEV];
static __device__ int   d_lvl_nodes[NLEV*CAP];
static __device__ float d_lp[B_];
static __device__ float* d_hsrc[B_*64*3];
static __device__ float* d_csrc[B_*64*3];
static __device__ int      d_maxlvl;
static __device__ unsigned d_bar_lstm;
static __device__ unsigned d_bar_tree;

__device__ __forceinline__ float sigf(float x){ return 1.f/(1.f+expf(-x)); }

// global barrier: monotonic counter, per-block local target
__device__ __forceinline__ void gbarrier(unsigned* bar, unsigned& barno, unsigned grid){
  __syncthreads();
  if (threadIdx.x == 0){
    __threadfence();
    barno += grid;
    atomicAdd(bar, 1u);
    while (*(volatile unsigned*)bar < barno) __nanosleep(64);
    __threadfence();
  }
  __syncthreads();
}

// ---------------- K0: reset ------------------------------------------------------
__global__ void k_init(){
  for (int i = threadIdx.x; i < 1024; i += blockDim.x) d_zero[i] = 0.f;
  if (threadIdx.x == 0){ d_maxlvl = 0; d_bar_lstm = 0u; d_bar_tree = 0u; }
}

// ---------------- K1: xg = emb @ w_ih^T + b_ih + b_hh ----------------------------
__global__ void k_xg(const float* __restrict__ A, const float* __restrict__ W,
                     const float* __restrict__ b1, const float* __restrict__ b2){
  __shared__ __align__(16) float As[16*68];
  __shared__ __align__(16) float Bs[16*68];
  int m0 = blockIdx.y*64, n0 = blockIdx.x*64;
  int t = threadIdx.x;
  int tx = t & 15, ty = t >> 4;
  float acc[4][4];
  #pragma unroll
  for (int i=0;i<4;i++){
    #pragma unroll
    for (int j=0;j<4;j++) acc[i][j]=0.f;
  }
  int lk = t & 15, lm = t >> 4;
  for (int k0=0;k0<1024;k0+=16){
    #pragma unroll
    for (int i=0;i<4;i++){
      int m = lm + i*16;
      As[lk*68+m] = A[(m0+m)*1024 + k0 + lk];
      Bs[lk*68+m] = W[(n0+m)*1024 + k0 + lk];
    }
    __syncthreads();
    #pragma unroll
    for (int k=0;k<16;k++){
      float4 a = *(const float4*)&As[k*68 + ty*4];
      float4 b = *(const float4*)&Bs[k*68 + tx*4];
      acc[0][0]+=a.x*b.x; acc[0][1]+=a.x*b.y; acc[0][2]+=a.x*b.z; acc[0][3]+=a.x*b.w;
      acc[1][0]+=a.y*b.x; acc[1][1]+=a.y*b.y; acc[1][2]+=a.y*b.z; acc[1][3]+=a.y*b.w;
      acc[2][0]+=a.z*b.x; acc[2][1]+=a.z*b.y; acc[2][2]+=a.z*b.z; acc[2][3]+=a.z*b.w;
      acc[3][0]+=a.w*b.x; acc[3][1]+=a.w*b.y; acc[3][2]+=a.w*b.z; acc[3][3]+=a.w*b.w;
    }
    __syncthreads();
  }
  #pragma unroll
  for (int i=0;i<4;i++){
    int m = m0 + ty*4 + i;
    int n = n0 + tx*4;
    float4 o;
    o.x = acc[i][0]+b1[n+0]+b2[n+0];
    o.y = acc[i][1]+b1[n+1]+b2[n+1];
    o.z = acc[i][2]+b1[n+2]+b2[n+2];
    o.w = acc[i][3]+b1[n+3]+b2[n+3];
    *(float4*)&d_xg[m*4096+n] = o;
  }
}

// ---------------- K2: rank scores ------------------------------------------------
__global__ void k_rank(const float* __restrict__ emb, const float* __restrict__ w1,
                       const float* __restrict__ w2){
  __shared__ __align__(16) float es[1024*8];
  __shared__ float red[8*128];
  int r0 = blockIdx.x*8;
  for (int idx = threadIdx.x; idx < 8192; idx += 128){
    int r = idx >> 10, k = idx & 1023;
    es[k*8+r] = emb[(r0+r)*1024 + k];
  }
  __syncthreads();
  int j = threadIdx.x;
  const float4* wr = (const float4*)(w1 + j*1024);
  float acc[8];
  #pragma unroll
  for (int r=0;r<8;r++) acc[r]=0.f;
  for (int k4=0;k4<256;k4++){
    float4 w = wr[k4];
    int kb = k4*4;
    #pragma unroll
    for (int q=0;q<4;q++){
      float wv = (q==0)?w.x:(q==1)?w.y:(q==2)?w.z:w.w;
      float4 e0 = *(const float4*)&es[(kb+q)*8];
      float4 e1 = *(const float4*)&es[(kb+q)*8+4];
      acc[0]+=e0.x*wv; acc[1]+=e0.y*wv; acc[2]+=e0.z*wv; acc[3]+=e0.w*wv;
      acc[4]+=e1.x*wv; acc[5]+=e1.y*wv; acc[6]+=e1.z*wv; acc[7]+=e1.w*wv;
    }
  }
  float w2j = w2[j];
  #pragma unroll
  for (int r=0;r<8;r++) red[r*128+j] = fmaxf(acc[r],0.f)*w2j;
  __syncthreads();
  if (threadIdx.x < 8){
    float s = 0.f;
    for (int jj=0;jj<128;jj++) s += red[threadIdx.x*128+jj];
    d_sc[r0+threadIdx.x] = s;
  }
}

// ---------------- K3: greedy tree build ------------------------------------------
__global__ void k_build(const int* __restrict__ length){
  int t = threadIdx.x;
  if (t == 0){ for (int l=0;l<NLEV;l++) d_lvl_cnt[l] = 0; }
  __syncthreads();
  if (t >= B_) return;
  int b = t;
  int len = length[b];
  const float* sc = d_sc + b*64;
  int ss[70], se[70], spar[70], sisl[70];
  int sp = 0, nn = 0;
  ss[0]=0; se[0]=len; spar[0]=-1; sisl[0]=0; sp=1;
  float lp = 0.f;
  int lvl[64];
  while (sp > 0){
    sp--;
    int s=ss[sp], e=se[sp], par=spar[sp], isl=sisl[sp];
    int idx = nn++;
    int pos = s; float best = sc[s];
    for (int i=s+1;i<e;i++){ float v=sc[i]; if (v>best){best=v; pos=i;} }
    float sum = 0.f;
    for (int i=s;i<e;i++) sum += expf(sc[i]-best);
    lp += (float)(e-s) * (sc[pos] - best - logf(sum));
    d_npos[b*64+idx] = pos;
    if (par >= 0){ if (isl) d_nleft[b*64+par]=idx; else d_nright[b*64+par]=idx; }
    int lc = (pos<=s)   ? -1 : ((pos==s+1)  ? 1024+s       : -2);
    int rc = (pos+1>=e) ? -1 : ((pos+2==e)  ? 1024+(pos+1) : -2);
    d_nleft[b*64+idx]  = lc;
    d_nright[b*64+idx] = rc;
    if (rc == -2){ ss[sp]=pos+1; se[sp]=e;   spar[sp]=idx; sisl[sp]=0; sp++; }
    if (lc == -2){ ss[sp]=s;     se[sp]=pos; spar[sp]=idx; sisl[sp]=1; sp++; }
  }
  d_lp[b] = lp;
  int mymax = 0;
  for (int i=nn-1;i>=0;i--){
    int lv = 0;
    int lc = d_nleft[b*64+i];  if (lc>=0 && lc<1024 && lvl[lc]>lv) lv = lvl[lc];
    int rc = d_nright[b*64+i]; if (rc>=0 && rc<1024 && lvl[rc]>lv) lv = lvl[rc];
    lvl[i] = lv + 1;
    if (lvl[i] > mymax) mymax = lvl[i];
    int slot = atomicAdd(&d_lvl_cnt[lv], 1);
    d_lvl_nodes[lv*CAP + slot] = (b<<8) | i;
  }
  atomicMax(&d_maxlvl, mymax);
  for (int i=0;i<nn;i++){
    int lc = d_nleft[b*64+i], rc = d_nright[b*64+i], pos = d_npos[b*64+i];
    int base = (b*64+i)*3;
    d_hsrc[base+0] = (lc==-1)? d_zero : (lc>=1024 ? d_hs+(b*64+lc-1024)*1024 : d_nodeh+(b*64+lc)*1024);
    d_csrc[base+0] = (lc==-1)? d_zero : (lc>=1024 ? d_cs+(b*64+lc-1024)*1024 : d_nodec+(b*64+lc)*1024);
    d_hsrc[base+1] = (rc==-1)? d_zero : (rc>=1024 ? d_hs+(b*64+rc-1024)*1024 : d_nodeh+(b*64+rc)*1024);
    d_csrc[base+1] = (rc==-1)? d_zero : (rc>=1024 ? d_cs+(b*64+rc-1024)*1024 : d_nodec+(b*64+rc)*1024);
    d_hsrc[base+2] = d_hs + (b*64+pos)*1024;
    d_csrc[base+2] = d_cs + (b*64+pos)*1024;
  }
}

// ---------------- K4: persistent LSTM (all 64 steps, global barrier) -------------
__global__ void k_lstm_p(const float* __restrict__ whh){
  __shared__ __align__(16) float Ws[128*36];
  __shared__ __align__(16) float Hs[128*20];
  __shared__ float Red[8*32*17];
  __shared__ float Gs[512];
  int u0 = blockIdx.x*8;
  int tid = threadIdx.x;
  unsigned barno = 0;
  for (int t = 0; t < 64; t++){
    if (t > 0){
      int combo = tid & 31, ks = tid >> 5;
      int cg = combo & 7, bg = combo >> 3;
      float acc[4][4];
      #pragma unroll
      for (int i=0;i<4;i++){
        #pragma unroll
        for (int j=0;j<4;j++) acc[i][j]=0.f;
      }
      int wcol = tid & 31, wkq = tid >> 5;
      int gcol = (wcol>>3)*1024 + u0 + (wcol&7);
      int hb = tid & 15, hkq = tid >> 4;
      const float* hrow = d_hs + (hb*64 + t-1)*1024;
      for (int kt=0; kt<8; kt++){
        int kb = kt*128;
        {
          const float4* wsrc = (const float4*)(whh + gcol*1024 + kb + wkq*16);
          #pragma unroll
          for (int j=0;j<4;j++){
            float4 v = wsrc[j];
            int k = wkq*16 + j*4;
            Ws[(k+0)*36+wcol]=v.x; Ws[(k+1)*36+wcol]=v.y;
            Ws[(k+2)*36+wcol]=v.z; Ws[(k+3)*36+wcol]=v.w;
          }
        }
        {
          const float4* hs4 = (const float4*)(hrow + kb + hkq*8);
          #pragma unroll
          for (int j=0;j<2;j++){
            float4 v = hs4[j];
            int k = hkq*8 + j*4;
            Hs[(k+0)*20+hb]=v.x; Hs[(k+1)*20+hb]=v.y;
            Hs[(k+2)*20+hb]=v.z; Hs[(k+3)*20+hb]=v.w;
          }
        }
        __syncthreads();
        #pragma unroll
        for (int i=0;i<16;i++){
          int k = ks*16 + i;
          float4 w = *(const float4*)&Ws[k*36 + cg*4];
          float4 h = *(const float4*)&Hs[k*20 + bg*4];
          acc[0][0]+=w.x*h.x; acc[0][1]+=w.x*h.y; acc[0][2]+=w.x*h.z; acc[0][3]+=w.x*h.w;
          acc[1][0]+=w.y*h.x; acc[1][1]+=w.y*h.y; acc[1][2]+=w.y*h.z; acc[1][3]+=w.y*h.w;
          acc[2][0]+=w.z*h.x; acc[2][1]+=w.z*h.y; acc[2][2]+=w.z*h.z; acc[2][3]+=w.z*h.w;
          acc[3][0]+=w.w*h.x; acc[3][1]+=w.w*h.y; acc[3][2]+=w.w*h.z; acc[3][3]+=w.w*h.w;
        }
        __syncthreads();
      }
      #pragma unroll
      for (int ci=0;ci<4;ci++){
        #pragma unroll
        for (int bi=0;bi<4;bi++)
          Red[(ks*32 + cg*4+ci)*17 + bg*4+bi] = acc[ci][bi];
      }
      __syncthreads();
      #pragma unroll
      for (int q=0;q<2;q++){
        int o = tid + q*256;
        int col = o >> 4, b = o & 15;
        float s = 0.f;
        #pragma unroll
        for (int s8=0;s8<8;s8++) s += Red[(s8*32+col)*17 + b];
        Gs[o] = s;
      }
      __syncthreads();
    } else {
      Gs[tid] = 0.f; Gs[tid+256] = 0.f;
      __syncthreads();
    }
    if (tid < 128){
      int u = tid >> 4, bb = tid & 15;
      const float* xg = d_xg + (bb*64+t)*4096 + u0 + u;
      float gi = Gs[(0*8+u)*16+bb] + xg[0];
      float gf = Gs[(1*8+u)*16+bb] + xg[1024];
      float gg = Gs[(2*8+u)*16+bb] + xg[2048];
      float go = Gs[(3*8+u)*16+bb] + xg[3072];
      float cp = (t>0)? d_cs[(bb*64+t-1)*1024 + u0+u] : 0.f;
      float c = sigf(gf)*cp + sigf(gi)*tanhf(gg);
      float h = sigf(go)*tanhf(c);
      d_hs[(bb*64+t)*1024 + u0+u] = h;
      d_cs[(bb*64+t)*1024 + u0+u] = c;
    }
    gbarrier(&d_bar_lstm, barno, LSTM_GRID);
  }
}

// ---------------- K5: persistent tree phase (gemm + epilogue, all rounds) --------
__global__ void k_tree_p(const float* __restrict__ tlw, const float* __restrict__ tlb,
                         float* __restrict__ out){
  __shared__ __align__(16) float As[32*20];
  __shared__ __align__(16) float Bs[32*132];
  __shared__ const float* ap[16];
  __shared__ int s_nz;
  int tid = threadIdx.x;
  int tx = tid & 31, ty = tid >> 5;
  unsigned barno = 0;
  int maxlvl = d_maxlvl;
  for (int r = 0; r < maxlvl; r++){
    int count = d_lvl_cnt[r];
    if (count > 8){
      // ---- main path: 16-row m-groups ----
      int mgroups = (count + 15) >> 4;
      int total = mgroups * 144;                 // 48 n-tiles x 3 kz per m-group
      for (int w = blockIdx.x; w < total; w += gridDim.x){
        int mg = w / 144;
        int rem = w - mg*144;
        int kz = rem / 48;
        int nt = rem - kz*48;
        int n0 = nt*128;
        if (tid == 0) s_nz = 0;
        __syncthreads();
        if (tid < 16){
          int li = mg*16 + tid;
          const float* p = d_zero;
          if (li < count){
            int node = d_lvl_nodes[r*CAP + li];
            p = d_hsrc[((node>>8)*64 + (node&255))*3 + kz];
          }
          ap[tid] = p;
          if (p != d_zero) atomicOr(&s_nz, 1);
        }
        __syncthreads();
        if (!s_nz){
          float4 z = make_float4(0.f,0.f,0.f,0.f);
          #pragma unroll
          for (int i=0;i<4;i++){
            int row = mg*16 + ty*4 + i;
            __stcg((float4*)&d_Gp[kz][(size_t)row*6144 + n0 + tx*4], z);
          }
          __syncthreads();
          continue;
        }
        float acc[4][4];
        #pragma unroll
        for (int i=0;i<4;i++){
          #pragma unroll
          for (int j=0;j<4;j++) acc[i][j]=0.f;
        }
        int am = tid & 15, akq = tid >> 4;       // A loader mapping
        for (int kt=0; kt<32; kt++){
          int kl = kt*32;
          {
            float4 v = *(const float4*)(ap[am] + kl + akq*4);
            As[(akq*4+0)*20+am]=v.x; As[(akq*4+1)*20+am]=v.y;
            As[(akq*4+2)*20+am]=v.z; As[(akq*4+3)*20+am]=v.w;
          }
          {
            const float4* src = (const float4*)(tlw + (size_t)(n0+tid)*3072 + kz*1024 + kl);
            #pragma unroll
            for (int j=0;j<8;j++){
              float4 v = src[j];
              int k = j*4;
              Bs[(k+0)*132+tid]=v.x; Bs[(k+1)*132+tid]=v.y;
              Bs[(k+2)*132+tid]=v.z; Bs[(k+3)*132+tid]=v.w;
            }
          }
          __syncthreads();
          #pragma unroll
          for (int k=0;k<32;k++){
            float4 a = *(const float4*)&As[k*20 + ty*4];
            float4 b = *(const float4*)&Bs[k*132 + tx*4];
            acc[0][0]+=a.x*b.x; acc[0][1]+=a.x*b.y; acc[0][2]+=a.x*b.z; acc[0][3]+=a.x*b.w;
            acc[1][0]+=a.y*b.x; acc[1][1]+=a.y*b.y; acc[1][2]+=a.y*b.z; acc[1][3]+=a.y*b.w;
            acc[2][0]+=a.z*b.x; acc[2][1]+=a.z*b.y; acc[2][2]+=a.z*b.z; acc[2][3]+=a.z*b.w;
            acc[3][0]+=a.w*b.x; acc[3][1]+=a.w*b.y; acc[3][2]+=a.w*b.z; acc[3][3]+=a.w*b.w;
          }
          __syncthreads();
        }
        #pragma unroll
        for (int i=0;i<4;i++){
          int row = mg*16 + ty*4 + i;
          float4 o = make_float4(acc[i][0],acc[i][1],acc[i][2],acc[i][3]);
          __stcg((float4*)&d_Gp[kz][(size_t)row*6144 + n0 + tx*4], o);
        }
        __syncthreads();
      }
    } else {
      // ---- small-count path: 4-row m-groups ----
      int mg4 = (count + 3) >> 2;
      int total4 = mg4 * 144;
      for (int w = blockIdx.x; w < total4; w += gridDim.x){
        int mg = w / 144;
        int rem = w - mg*144;
        int kz = rem / 48;
        int nt = rem - kz*48;
        int n0 = nt*128;
        if (tid == 0) s_nz = 0;
        __syncthreads();
        if (tid < 4){
          int li = mg*4 + tid;
          const float* p = d_zero;
          if (li < count){
            int node = d_lvl_nodes[r*CAP + li];
            p = d_hsrc[((node>>8)*64 + (node&255))*3 + kz];
          }
          ap[tid] = p;
          if (p != d_zero) atomicOr(&s_nz, 1);
        }
        __syncthreads();
        if (!s_nz){
          int row = mg*4 + ty;
          __stcg((float4*)&d_Gp[kz][(size_t)row*6144 + n0 + tx*4],
                 make_float4(0.f,0.f,0.f,0.f));
          __syncthreads();
          continue;
        }
        float acc4[4] = {0.f,0.f,0.f,0.f};
        for (int kt=0; kt<32; kt++){
          int kl = kt*32;
          As[tx*20 + ty] = ap[ty][kl + tx];       // warp per row, lane per k
          {
            const float4* src = (const float4*)(tlw + (size_t)(n0+tid)*3072 + kz*1024 + kl);
            #pragma unroll
            for (int j=0;j<8;j++){
              float4 v = src[j];
              int k = j*4;
              Bs[(k+0)*132+tid]=v.x; Bs[(k+1)*132+tid]=v.y;
              Bs[(k+2)*132+tid]=v.z; Bs[(k+3)*132+tid]=v.w;
            }
          }
          __syncthreads();
          #pragma unroll
          for (int k=0;k<32;k++){
            float a = As[k*20 + ty];
            float4 b = *(const float4*)&Bs[k*132 + tx*4];
            acc4[0]+=a*b.x; acc4[1]+=a*b.y; acc4[2]+=a*b.z; acc4[3]+=a*b.w;
          }
          __syncthreads();
        }
        {
          int row = mg*4 + ty;
          __stcg((float4*)&d_Gp[kz][(size_t)row*6144 + n0 + tx*4],
                 make_float4(acc4[0],acc4[1],acc4[2],acc4[3]));
        }
        __syncthreads();
      }
    }
    gbarrier(&d_bar_tree, barno, TREE_GRID);
    // epilogue: sum 3 k-split partials + TreeLSTM cell
    for (int li = blockIdx.x; li < count; li += gridDim.x){
      int node = d_lvl_nodes[r*CAP + li];
      int b = node >> 8, idx = node & 255;
      int base = (b*64+idx)*3;
      const float* cl = d_csrc[base+0];
      const float* cr = d_csrc[base+1];
      const float* cm = d_csrc[base+2];
      const float* G0 = d_Gp[0] + (size_t)li*6144;
      const float* G1 = d_Gp[1] + (size_t)li*6144;
      const float* G2 = d_Gp[2] + (size_t)li*6144;
      float* nh = d_nodeh + (b*64+idx)*1024;
      float* nc = d_nodec + (b*64+idx)*1024;
      for (int u = tid; u < 1024; u += blockDim.x){
        float gi  = __ldcg(G0+u)      + __ldcg(G1+u)      + __ldcg(G2+u)      + tlb[u];
        float gfl = __ldcg(G0+1024+u) + __ldcg(G1+1024+u) + __ldcg(G2+1024+u) + tlb[1024+u];
        float gfr = __ldcg(G0+2048+u) + __ldcg(G1+2048+u) + __ldcg(G2+2048+u) + tlb[2048+u];
        float gfm = __ldcg(G0+3072+u) + __ldcg(G1+3072+u) + __ldcg(G2+3072+u) + tlb[3072+u];
        float gu  = __ldcg(G0+4096+u) + __ldcg(G1+4096+u) + __ldcg(G2+4096+u) + tlb[4096+u];
        float go  = __ldcg(G0+5120+u) + __ldcg(G1+5120+u) + __ldcg(G2+5120+u) + tlb[5120+u];
        float c = sigf(gfl)*cl[u] + sigf(gfr)*cr[u] + sigf(gfm)*cm[u] + sigf(gi)*tanhf(gu);
        float h = sigf(go)*tanhf(c);
        nh[u] = h; nc[u] = c;
      }
    }
    gbarrier(&d_bar_tree, barno, TREE_GRID);
  }
  // output: root h, root c, lp
  for (int i = blockIdx.x*blockDim.x + tid; i < 16384; i += gridDim.x*blockDim.x){
    int b = i >> 10, u = i & 1023;
    out[i]         = d_nodeh[(b*64)*1024 + u];
    out[16384 + i] = d_nodec[(b*64)*1024 + u];
  }
  if (blockIdx.x == 0 && tid < 16) out[32768 + tid] = d_lp[tid];
}

extern "C" void kernel_launch(void* const* d_in, const int* in_sizes, int n_in,
                              void* d_out, int out_size){
  const float* emb    = (const float*)d_in[0];
  const int*   length = (const int*)  d_in[2];
  const float* w_ih   = (const float*)d_in[3];
  const float* w_hh   = (const float*)d_in[4];
  const float* b_ih   = (const float*)d_in[5];
  const float* b_hh   = (const float*)d_in[6];
  const float* tl_w   = (const float*)d_in[7];
  const float* tl_b   = (const float*)d_in[8];
  const float* rw1    = (const float*)d_in[9];
  const float* rw2    = (const float*)d_in[10];
  float* out = (float*)d_out;

  k_init<<<1, 256>>>();
  k_xg<<<dim3(64,16), 256>>>(emb, w_ih, b_ih, b_hh);
  k_rank<<<128, 128>>>(emb, rw1, rw2);
  k_build<<<1, 64>>>(length);
  k_lstm_p<<<LSTM_GRID, 256>>>(w_hh);
  k_tree_p<<<TREE_GRID, 128>>>(tl_w, tl_b, out);
}

// round 10
// speedup vs baseline: 1.1732x; 1.1732x over previous
#include <cuda_runtime.h>
#include <math.h>

#define B_ 16
#define L_ 64
#define NLEV 63
#define CAP 512
#define TREE_GRID 296
#define LSTM_GRID 128

// ---------------- device scratch (static globals) --------------------------------
static __device__ __align__(256) float d_xg[B_*L_*4096];
static __device__ __align__(256) float d_hs[B_*L_*1024];
static __device__ __align__(256) float d_cs[B_*L_*1024];
static __device__ __align__(256) float d_nodeh[B_*64*1024];
static __device__ __align__(256) float d_nodec[B_*64*1024];
static __device__ __align__(256) float d_Gp[3][CAP*6144];
static __device__ __align__(256) float d_zero[1024];
static __device__ float d_sc[B_*L_];
static __device__ int   d_npos[B_*64];
static __device__ int   d_nleft[B_*64];
static __device__ int   d_nright[B_*64];
static __device__ int   d_lvl_cnt[NLEV];
static __device__ int   d_lvl_nodes[NLEV*CAP];
static __device__ float d_lp[B_];
static __device__ float* d_hsrc[B_*64*3];
static __device__ float* d_csrc[B_*64*3];
static __device__ int      d_maxlvl;
static __device__ unsigned d_bar_lstm;
static __device__ unsigned d_bar_tree;

__device__ __forceinline__ float sigf(float x){ return 1.f/(1.f+expf(-x)); }

__device__ __forceinline__ void cpa16(float* smem, const float* g){
  unsigned s = (unsigned)__cvta_generic_to_shared(smem);
  asm volatile("cp.async.cg.shared.global [%0], [%1], 16;" :: "r"(s), "l"(g));
}

// global barrier: monotonic counter, per-block local target
__device__ __forceinline__ void gbarrier(unsigned* bar, unsigned& barno, unsigned grid){
  __syncthreads();
  if (threadIdx.x == 0){
    __threadfence();
    barno += grid;
    atomicAdd(bar, 1u);
    while (*(volatile unsigned*)bar < barno) __nanosleep(64);
    __threadfence();
  }
  __syncthreads();
}

// ---------------- K0: reset ------------------------------------------------------
__global__ void k_init(){
  for (int i = threadIdx.x; i < 1024; i += blockDim.x) d_zero[i] = 0.f;
  if (threadIdx.x == 0){ d_maxlvl = 0; d_bar_lstm = 0u; d_bar_tree = 0u; }
}

// ---------------- K1: xg = emb @ w_ih^T + b_ih + b_hh ----------------------------
__global__ void k_xg(const float* __restrict__ A, const float* __restrict__ W,
                     const float* __restrict__ b1, const float* __restrict__ b2){
  __shared__ __align__(16) float As[16*68];
  __shared__ __align__(16) float Bs[16*68];
  int m0 = blockIdx.y*64, n0 = blockIdx.x*64;
  int t = threadIdx.x;
  int tx = t & 15, ty = t >> 4;
  float acc[4][4];
  #pragma unroll
  for (int i=0;i<4;i++){
    #pragma unroll
    for (int j=0;j<4;j++) acc[i][j]=0.f;
  }
  int lk = t & 15, lm = t >> 4;
  for (int k0=0;k0<1024;k0+=16){
    #pragma unroll
    for (int i=0;i<4;i++){
      int m = lm + i*16;
      As[lk*68+m] = A[(m0+m)*1024 + k0 + lk];
      Bs[lk*68+m] = W[(n0+m)*1024 + k0 + lk];
    }
    __syncthreads();
    #pragma unroll
    for (int k=0;k<16;k++){
      float4 a = *(const float4*)&As[k*68 + ty*4];
      float4 b = *(const float4*)&Bs[k*68 + tx*4];
      acc[0][0]+=a.x*b.x; acc[0][1]+=a.x*b.y; acc[0][2]+=a.x*b.z; acc[0][3]+=a.x*b.w;
      acc[1][0]+=a.y*b.x; acc[1][1]+=a.y*b.y; acc[1][2]+=a.y*b.z; acc[1][3]+=a.y*b.w;
      acc[2][0]+=a.z*b.x; acc[2][1]+=a.z*b.y; acc[2][2]+=a.z*b.z; acc[2][3]+=a.z*b.w;
      acc[3][0]+=a.w*b.x; acc[3][1]+=a.w*b.y; acc[3][2]+=a.w*b.z; acc[3][3]+=a.w*b.w;
    }
    __syncthreads();
  }
  #pragma unroll
  for (int i=0;i<4;i++){
    int m = m0 + ty*4 + i;
    int n = n0 + tx*4;
    float4 o;
    o.x = acc[i][0]+b1[n+0]+b2[n+0];
    o.y = acc[i][1]+b1[n+1]+b2[n+1];
    o.z = acc[i][2]+b1[n+2]+b2[n+2];
    o.w = acc[i][3]+b1[n+3]+b2[n+3];
    *(float4*)&d_xg[m*4096+n] = o;
  }
}

// ---------------- K2: rank scores ------------------------------------------------
__global__ void k_rank(const float* __restrict__ emb, const float* __restrict__ w1,
                       const float* __restrict__ w2){
  __shared__ __align__(16) float es[1024*8];
  __shared__ float red[8*128];
  int r0 = blockIdx.x*8;
  for (int idx = threadIdx.x; idx < 8192; idx += 128){
    int r = idx >> 10, k = idx & 1023;
    es[k*8+r] = emb[(r0+r)*1024 + k];
  }
  __syncthreads();
  int j = threadIdx.x;
  const float4* wr = (const float4*)(w1 + j*1024);
  float acc[8];
  #pragma unroll
  for (int r=0;r<8;r++) acc[r]=0.f;
  for (int k4=0;k4<256;k4++){
    float4 w = wr[k4];
    int kb = k4*4;
    #pragma unroll
    for (int q=0;q<4;q++){
      float wv = (q==0)?w.x:(q==1)?w.y:(q==2)?w.z:w.w;
      float4 e0 = *(const float4*)&es[(kb+q)*8];
      float4 e1 = *(const float4*)&es[(kb+q)*8+4];
      acc[0]+=e0.x*wv; acc[1]+=e0.y*wv; acc[2]+=e0.z*wv; acc[3]+=e0.w*wv;
      acc[4]+=e1.x*wv; acc[5]+=e1.y*wv; acc[6]+=e1.z*wv; acc[7]+=e1.w*wv;
    }
  }
  float w2j = w2[j];
  #pragma unroll
  for (int r=0;r<8;r++) red[r*128+j] = fmaxf(acc[r],0.f)*w2j;
  __syncthreads();
  if (threadIdx.x < 8){
    float s = 0.f;
    for (int jj=0;jj<128;jj++) s += red[threadIdx.x*128+jj];
    d_sc[r0+threadIdx.x] = s;
  }
}

// ---------------- K3: greedy tree build (warp per batch) -------------------------
__global__ void k_build(const int* __restrict__ length){
  int tid = threadIdx.x;
  if (tid < NLEV) d_lvl_cnt[tid] = 0;
  __syncthreads();
  int w = tid >> 5, lane = tid & 31;
  if (w >= B_) return;
  int b = w;
  int len = length[b];
  const float* sc = d_sc + b*64;
  int ss[70], se[70], spar[70], sisl[70];
  int sp = 1, nn = 0;
  ss[0]=0; se[0]=len; spar[0]=-1; sisl[0]=0;
  float lp = 0.f;
  while (sp > 0){
    sp--;
    int s=ss[sp], e=se[sp], par=spar[sp], isl=sisl[sp];
    int idx = nn++;
    // warp-parallel first-argmax
    float bv = -3.0e38f; int bi = e;
    for (int i=s+lane; i<e; i+=32){
      float v = sc[i];
      if (v>bv || (v==bv && i<bi)){ bv=v; bi=i; }
    }
    #pragma unroll
    for (int off=16; off; off>>=1){
      float ov = __shfl_down_sync(0xffffffffu, bv, off);
      int   oi = __shfl_down_sync(0xffffffffu, bi, off);
      if (ov>bv || (ov==bv && oi<bi)){ bv=ov; bi=oi; }
    }
    bv = __shfl_sync(0xffffffffu, bv, 0);
    bi = __shfl_sync(0xffffffffu, bi, 0);
    // warp-parallel exp-sum
    float sum = 0.f;
    for (int i=s+lane; i<e; i+=32) sum += expf(sc[i]-bv);
    #pragma unroll
    for (int off=16; off; off>>=1) sum += __shfl_down_sync(0xffffffffu, sum, off);
    sum = __shfl_sync(0xffffffffu, sum, 0);
    int pos = bi;
    lp += (float)(e-s) * (sc[pos] - bv - logf(sum));
    if (lane == 0){
      d_npos[b*64+idx] = pos;
      if (par >= 0){ if (isl) d_nleft[b*64+par]=idx; else d_nright[b*64+par]=idx; }
    }
    int lc = (pos<=s)   ? -1 : ((pos==s+1)  ? 1024+s       : -2);
    int rc = (pos+1>=e) ? -1 : ((pos+2==e)  ? 1024+(pos+1) : -2);
    if (lane == 0){ d_nleft[b*64+idx]=lc; d_nright[b*64+idx]=rc; }
    if (rc == -2){ ss[sp]=pos+1; se[sp]=e;   spar[sp]=idx; sisl[sp]=0; sp++; }
    if (lc == -2){ ss[sp]=s;     se[sp]=pos; spar[sp]=idx; sisl[sp]=1; sp++; }
  }
  if (lane == 0){
    d_lp[b] = lp;
    int lvl[64];
    int mymax = 0;
    for (int i=nn-1;i>=0;i--){
      int lv = 0;
      int lc = d_nleft[b*64+i];  if (lc>=0 && lc<1024 && lvl[lc]>lv) lv = lvl[lc];
      int rc = d_nright[b*64+i]; if (rc>=0 && rc<1024 && lvl[rc]>lv) lv = lvl[rc];
      lvl[i] = lv + 1;
      if (lvl[i] > mymax) mymax = lvl[i];
      int slot = atomicAdd(&d_lvl_cnt[lv], 1);
      d_lvl_nodes[lv*CAP + slot] = (b<<8) | i;
    }
    atomicMax(&d_maxlvl, mymax);
    for (int i=0;i<nn;i++){
      int lc = d_nleft[b*64+i], rc = d_nright[b*64+i], pos = d_npos[b*64+i];
      int base = (b*64+i)*3;
      d_hsrc[base+0] = (lc==-1)? d_zero : (lc>=1024 ? d_hs+(b*64+lc-1024)*1024 : d_nodeh+(b*64+lc)*1024);
      d_csrc[base+0] = (lc==-1)? d_zero : (lc>=1024 ? d_cs+(b*64+lc-1024)*1024 : d_nodec+(b*64+lc)*1024);
      d_hsrc[base+1] = (rc==-1)? d_zero : (rc>=1024 ? d_hs+(b*64+rc-1024)*1024 : d_nodeh+(b*64+rc)*1024);
      d_csrc[base+1] = (rc==-1)? d_zero : (rc>=1024 ? d_cs+(b*64+rc-1024)*1024 : d_nodec+(b*64+rc)*1024);
      d_hsrc[base+2] = d_hs + (b*64+pos)*1024;
      d_csrc[base+2] = d_cs + (b*64+pos)*1024;
    }
  }
}

// ---------------- K4: persistent LSTM (all 64 steps, global barrier) -------------
__global__ void k_lstm_p(const float* __restrict__ whh){
  __shared__ __align__(16) float Ws[128*36];
  __shared__ __align__(16) float Hs[128*20];
  __shared__ float Red[8*32*17];
  __shared__ float Gs[512];
  int u0 = blockIdx.x*8;
  int tid = threadIdx.x;
  unsigned barno = 0;
  for (int t = 0; t < 64; t++){
    if (t > 0){
      int combo = tid & 31, ks = tid >> 5;
      int cg = combo & 7, bg = combo >> 3;
      float acc[4][4];
      #pragma unroll
      for (int i=0;i<4;i++){
        #pragma unroll
        for (int j=0;j<4;j++) acc[i][j]=0.f;
      }
      int wcol = tid & 31, wkq = tid >> 5;
      int gcol = (wcol>>3)*1024 + u0 + (wcol&7);
      int hb = tid & 15, hkq = tid >> 4;
      const float* hrow = d_hs + (hb*64 + t-1)*1024;
      for (int kt=0; kt<8; kt++){
        int kb = kt*128;
        {
          const float4* wsrc = (const float4*)(whh + gcol*1024 + kb + wkq*16);
          #pragma unroll
          for (int j=0;j<4;j++){
            float4 v = wsrc[j];
            int k = wkq*16 + j*4;
            Ws[(k+0)*36+wcol]=v.x; Ws[(k+1)*36+wcol]=v.y;
            Ws[(k+2)*36+wcol]=v.z; Ws[(k+3)*36+wcol]=v.w;
          }
        }
        {
          const float4* hs4 = (const float4*)(hrow + kb + hkq*8);
          #pragma unroll
          for (int j=0;j<2;j++){
            float4 v = hs4[j];
            int k = hkq*8 + j*4;
            Hs[(k+0)*20+hb]=v.x; Hs[(k+1)*20+hb]=v.y;
            Hs[(k+2)*20+hb]=v.z; Hs[(k+3)*20+hb]=v.w;
          }
        }
        __syncthreads();
        #pragma unroll
        for (int i=0;i<16;i++){
          int k = ks*16 + i;
          float4 w = *(const float4*)&Ws[k*36 + cg*4];
          float4 h = *(const float4*)&Hs[k*20 + bg*4];
          acc[0][0]+=w.x*h.x; acc[0][1]+=w.x*h.y; acc[0][2]+=w.x*h.z; acc[0][3]+=w.x*h.w;
          acc[1][0]+=w.y*h.x; acc[1][1]+=w.y*h.y; acc[1][2]+=w.y*h.z; acc[1][3]+=w.y*h.w;
          acc[2][0]+=w.z*h.x; acc[2][1]+=w.z*h.y; acc[2][2]+=w.z*h.z; acc[2][3]+=w.z*h.w;
          acc[3][0]+=w.w*h.x; acc[3][1]+=w.w*h.y; acc[3][2]+=w.w*h.z; acc[3][3]+=w.w*h.w;
        }
        __syncthreads();
      }
      #pragma unroll
      for (int ci=0;ci<4;ci++){
        #pragma unroll
        for (int bi=0;bi<4;bi++)
          Red[(ks*32 + cg*4+ci)*17 + bg*4+bi] = acc[ci][bi];
      }
      __syncthreads();
      #pragma unroll
      for (int q=0;q<2;q++){
        int o = tid + q*256;
        int col = o >> 4, b = o & 15;
        float s = 0.f;
        #pragma unroll
        for (int s8=0;s8<8;s8++) s += Red[(s8*32+col)*17 + b];
        Gs[o] = s;
      }
      __syncthreads();
    } else {
      Gs[tid] = 0.f; Gs[tid+256] = 0.f;
      __syncthreads();
    }
    if (tid < 128){
      int u = tid >> 4, bb = tid & 15;
      const float* xg = d_xg + (bb*64+t)*4096 + u0 + u;
      float gi = Gs[(0*8+u)*16+bb] + xg[0];
      float gf = Gs[(1*8+u)*16+bb] + xg[1024];
      float gg = Gs[(2*8+u)*16+bb] + xg[2048];
      float go = Gs[(3*8+u)*16+bb] + xg[3072];
      float cp = (t>0)? d_cs[(bb*64+t-1)*1024 + u0+u] : 0.f;
      float c = sigf(gf)*cp + sigf(gi)*tanhf(gg);
      float h = sigf(go)*tanhf(c);
      d_hs[(bb*64+t)*1024 + u0+u] = h;
      d_cs[(bb*64+t)*1024 + u0+u] = c;
    }
    gbarrier(&d_bar_lstm, barno, LSTM_GRID);
  }
}

// ---------------- K5: persistent tree phase (cp.async pipelined GEMM) ------------
// A [m][k] stride 36, B [n][k] stride 36, double buffered; n = tx + 32j mapping
__global__ void k_tree_p(const float* __restrict__ tlw, const float* __restrict__ tlb,
                         float* __restrict__ out){
  __shared__ __align__(16) float As[2][16*36];
  __shared__ __align__(16) float Bs[2][128*36];
  __shared__ const float* ap[16];
  int tid = threadIdx.x;
  int tx = tid & 31, ty = tid >> 5;
  int am = tid >> 3, aseg = tid & 7;
  unsigned barno = 0;
  int maxlvl = d_maxlvl;
  for (int r = 0; r < maxlvl; r++){
    int count = d_lvl_cnt[r];
    int mgroups = (count + 15) >> 4;
    int total = mgroups * 144;                   // 48 n-tiles x 3 kz per m-group
    for (int w = blockIdx.x; w < total; w += gridDim.x){
      int mg = w / 144;
      int rem = w - mg*144;
      int kz = rem / 48;
      int nt = rem - kz*48;
      int n0 = nt*128;
      if (tid < 16){
        int li = mg*16 + tid;
        const float* p = d_zero;
        if (li < count){
          int node = d_lvl_nodes[r*CAP + li];
          p = d_hsrc[((node>>8)*64 + (node&255))*3 + kz];
        }
        ap[tid] = p;
      }
      __syncthreads();
      const float* bbase = tlw + (size_t)(n0+tid)*3072 + kz*1024;
      // prologue: tile 0 -> buf 0
      {
        cpa16(&As[0][am*36 + aseg*4], ap[am] + aseg*4);
        #pragma unroll
        for (int j=0;j<8;j++) cpa16(&Bs[0][tid*36 + j*4], bbase + j*4);
        asm volatile("cp.async.commit_group;");
      }
      float acc[4][4];
      #pragma unroll
      for (int i=0;i<4;i++){
        #pragma unroll
        for (int j=0;j<4;j++) acc[i][j]=0.f;
      }
      for (int kt=0; kt<32; kt++){
        int cur = kt & 1;
        if (kt < 31){
          int nb = (kt+1) & 1;
          int kl = (kt+1)*32;
          cpa16(&As[nb][am*36 + aseg*4], ap[am] + kl + aseg*4);
          #pragma unroll
          for (int j=0;j<8;j++) cpa16(&Bs[nb][tid*36 + j*4], bbase + kl + j*4);
          asm volatile("cp.async.commit_group;");
          asm volatile("cp.async.wait_group 1;");
        } else {
          asm volatile("cp.async.wait_group 0;");
        }
        __syncthreads();
        const float4* A4 = (const float4*)As[cur];
        const float4* B4 = (const float4*)Bs[cur];
        #pragma unroll
        for (int k4=0;k4<8;k4++){
          float4 a0 = A4[(ty*4+0)*9 + k4];
          float4 a1 = A4[(ty*4+1)*9 + k4];
          float4 a2 = A4[(ty*4+2)*9 + k4];
          float4 a3 = A4[(ty*4+3)*9 + k4];
          float4 b0 = B4[(tx     )*9 + k4];
          float4 b1 = B4[(tx+32  )*9 + k4];
          float4 b2 = B4[(tx+64  )*9 + k4];
          float4 b3 = B4[(tx+96  )*9 + k4];
          acc[0][0] += a0.x*b0.x + a0.y*b0.y + a0.z*b0.z + a0.w*b0.w;
          acc[0][1] += a0.x*b1.x + a0.y*b1.y + a0.z*b1.z + a0.w*b1.w;
          acc[0][2] += a0.x*b2.x + a0.y*b2.y + a0.z*b2.z + a0.w*b2.w;
          acc[0][3] += a0.x*b3.x + a0.y*b3.y + a0.z*b3.z + a0.w*b3.w;
          acc[1][0] += a1.x*b0.x + a1.y*b0.y + a1.z*b0.z + a1.w*b0.w;
          acc[1][1] += a1.x*b1.x + a1.y*b1.y + a1.z*b1.z + a1.w*b1.w;
          acc[1][2] += a1.x*b2.x + a1.y*b2.y + a1.z*b2.z + a1.w*b2.w;
          acc[1][3] += a1.x*b3.x + a1.y*b3.y + a1.z*b3.z + a1.w*b3.w;
          acc[2][0] += a2.x*b0.x + a2.y*b0.y + a2.z*b0.z + a2.w*b0.w;
          acc[2][1] += a2.x*b1.x + a2.y*b1.y + a2.z*b1.z + a2.w*b1.w;
          acc[2][2] += a2.x*b2.x + a2.y*b2.y + a2.z*b2.z + a2.w*b2.w;
          acc[2][3] += a2.x*b3.x + a2.y*b3.y + a2.z*b3.z + a2.w*b3.w;
          acc[3][0] += a3.x*b0.x + a3.y*b0.y + a3.z*b0.z + a3.w*b0.w;
          acc[3][1] += a3.x*b1.x + a3.y*b1.y + a3.z*b1.z + a3.w*b1.w;
          acc[3][2] += a3.x*b2.x + a3.y*b2.y + a3.z*b2.z + a3.w*b2.w;
          acc[3][3] += a3.x*b3.x + a3.y*b3.y + a3.z*b3.z + a3.w*b3.w;
        }
        __syncthreads();
      }
      #pragma unroll
      for (int i=0;i<4;i++){
        int row = mg*16 + ty*4 + i;
        float* dst = &d_Gp[kz][(size_t)row*6144 + n0];
        __stcg(dst + tx,      acc[i][0]);
        __stcg(dst + tx + 32, acc[i][1]);
        __stcg(dst + tx + 64, acc[i][2]);
        __stcg(dst + tx + 96, acc[i][3]);
      }
      __syncthreads();
    }
    gbarrier(&d_bar_tree, barno, TREE_GRID);
    // epilogue: sum 3 k-split partials + TreeLSTM cell
    for (int li = blockIdx.x; li < count; li += gridDim.x){
      int node = d_lvl_nodes[r*CAP + li];
      int b = node >> 8, idx = node & 255;
      int base = (b*64+idx)*3;
      const float* cl = d_csrc[base+0];
      const float* cr = d_csrc[base+1];
      const float* cm = d_csrc[base+2];
      const float* G0 = d_Gp[0] + (size_t)li*6144;
      const float* G1 = d_Gp[1] + (size_t)li*6144;
      const float* G2 = d_Gp[2] + (size_t)li*6144;
      float* nh = d_nodeh + (b*64+idx)*1024;
      float* nc = d_nodec + (b*64+idx)*1024;
      for (int u = tid; u < 1024; u += blockDim.x){
        float gi  = __ldcg(G0+u)      + __ldcg(G1+u)      + __ldcg(G2+u)      + tlb[u];
        float gfl = __ldcg(G0+1024+u) + __ldcg(G1+1024+u) + __ldcg(G2+1024+u) + tlb[1024+u];
        float gfr = __ldcg(G0+2048+u) + __ldcg(G1+2048+u) + __ldcg(G2+2048+u) + tlb[2048+u];
        float gfm = __ldcg(G0+3072+u) + __ldcg(G1+3072+u) + __ldcg(G2+3072+u) + tlb[3072+u];
        float gu  = __ldcg(G0+4096+u) + __ldcg(G1+4096+u) + __ldcg(G2+4096+u) + tlb[4096+u];
        float go  = __ldcg(G0+5120+u) + __ldcg(G1+5120+u) + __ldcg(G2+5120+u) + tlb[5120+u];
        float c = sigf(gfl)*cl[u] + sigf(gfr)*cr[u] + sigf(gfm)*cm[u] + sigf(gi)*tanhf(gu);
        float h = sigf(go)*tanhf(c);
        nh[u] = h; nc[u] = c;
      }
    }
    gbarrier(&d_bar_tree, barno, TREE_GRID);
  }
  // output: root h, root c, lp
  for (int i = blockIdx.x*blockDim.x + tid; i < 16384; i += gridDim.x*blockDim.x){
    int b = i >> 10, u = i & 1023;
    out[i]         = d_nodeh[(b*64)*1024 + u];
    out[16384 + i] = d_nodec[(b*64)*1024 + u];
  }
  if (blockIdx.x == 0 && tid < 16) out[32768 + tid] = d_lp[tid];
}

extern "C" void kernel_launch(void* const* d_in, const int* in_sizes, int n_in,
                              void* d_out, int out_size){
  const float* emb    = (const float*)d_in[0];
  const int*   length = (const int*)  d_in[2];
  const float* w_ih   = (const float*)d_in[3];
  const float* w_hh   = (const float*)d_in[4];
  const float* b_ih   = (const float*)d_in[5];
  const float* b_hh   = (const float*)d_in[6];
  const float* tl_w   = (const float*)d_in[7];
  const float* tl_b   = (const float*)d_in[8];
  const float* rw1    = (const float*)d_in[9];
  const float* rw2    = (const float*)d_in[10];
  float* out = (float*)d_out;

  k_init<<<1, 256>>>();
  k_xg<<<dim3(64,16), 256>>>(emb, w_ih, b_ih, b_hh);
  k_rank<<<128, 128>>>(emb, rw1, rw2);
  k_build<<<1, 512>>>(length);
  k_lstm_p<<<LSTM_GRID, 256>>>(w_hh);
  k_tree_p<<<TREE_GRID, 128>>>(tl_w, tl_b, out);
}